// round 7
// baseline (speedup 1.0000x reference)
#include <cuda_runtime.h>

#define BATCH 16
#define CIN   768
#define L0    4096
#define L1    2048
#define L2    1024

typedef unsigned long long u64;

__device__ __forceinline__ u64 pk2(float a, float b) {
    u64 r; asm("mov.b64 %0,{%1,%2};" : "=l"(r) : "f"(a), "f"(b)); return r;
}
__device__ __forceinline__ u64 spl(float a) { return pk2(a, a); }
__device__ __forceinline__ void fma2(u64& d, u64 a, u64 b) {
    asm("fma.rn.f32x2 %0,%1,%2,%0;" : "+l"(d) : "l"(a), "l"(b));
}
__device__ __forceinline__ float2 up2(u64 v) {
    float2 r; asm("mov.b64 {%0,%1},%2;" : "=f"(r.x), "=f"(r.y) : "l"(v)); return r;
}

__device__ float g_h1[BATCH * 32 * L1];
__device__ float g_A[BATCH * 64 * L2];
__device__ float g_B[BATCH * 64 * L2];
__device__ float g_C[BATCH * 64 * L2];
__device__ float g_d1[BATCH * 32 * L1];
__device__ float g_e2[512];

// ---- conv1: x(16,768,4096)->h1(16,32,2048), k4 s2 p1, ReLU -----------------
// 8 warps: og=wid>>1 (8 out-ch), half=wid&1 (time half). oi packed in f32x2.
__global__ __launch_bounds__(256) void conv1_k(const float* __restrict__ x,
                                               const float* __restrict__ w,
                                               const float* __restrict__ bias) {
    extern __shared__ float sm[];
    float* xe = sm;                 // [32][132] even inputs
    float* xo = sm + 32 * 132;      // [32][132] odd inputs
    float* ws = xo + 32 * 132;      // [32c*4k][32o]
    const int bb = blockIdx.y, t0 = blockIdx.x * 128;
    const int tid = threadIdx.x, lane = tid & 31, wid = tid >> 5;
    const int og = wid >> 1, half = wid & 1;
    const int tA = lane + 64 * half;

    u64 acc[4][2];
#pragma unroll
    for (int p = 0; p < 4; p++) { acc[p][0] = 0ull; acc[p][1] = 0ull; }

    for (int c0 = 0; c0 < CIN; c0 += 32) {
        for (int i = tid; i < 32 * 4 * 32; i += 256) {
            int k = i & 3, c = (i >> 2) & 31, o = i >> 7;
            ws[(c * 4 + k) * 32 + o] = w[((o * CIN) + c0 + c) * 4 + k];
        }
        for (int i = tid; i < 32 * 258; i += 256) {
            int c = i / 258, q = i - c * 258;
            int gp = 2 * t0 - 1 + q;
            float v = (gp >= 0 && gp < L0) ? x[((bb * CIN) + c0 + c) * L0 + gp] : 0.f;
            if (q & 1) xe[c * 132 + (q >> 1)] = v;
            else       xo[c * 132 + (q >> 1)] = v;
        }
        __syncthreads();
#pragma unroll 2
        for (int c = 0; c < 32; ++c) {
            const float* pe = &xe[c * 132];
            const float* po = &xo[c * 132];
            // taps for output t: k0=odd[t], k1=even[t], k2=odd[t+1], k3=even[t+1]
            u64 XA[4] = { spl(po[tA]), spl(pe[tA]), spl(po[tA + 1]), spl(pe[tA + 1]) };
            u64 XB[4] = { spl(po[tA + 32]), spl(pe[tA + 32]), spl(po[tA + 33]), spl(pe[tA + 33]) };
            const float* wb = &ws[c * 4 * 32 + og * 8];
#pragma unroll
            for (int k = 0; k < 4; k++) {
                u64 w0 = *(const u64*)&wb[k * 32 + 0];
                u64 w1 = *(const u64*)&wb[k * 32 + 2];
                u64 w2 = *(const u64*)&wb[k * 32 + 4];
                u64 w3 = *(const u64*)&wb[k * 32 + 6];
                fma2(acc[0][0], w0, XA[k]); fma2(acc[0][1], w0, XB[k]);
                fma2(acc[1][0], w1, XA[k]); fma2(acc[1][1], w1, XB[k]);
                fma2(acc[2][0], w2, XA[k]); fma2(acc[2][1], w2, XB[k]);
                fma2(acc[3][0], w3, XA[k]); fma2(acc[3][1], w3, XB[k]);
            }
        }
        __syncthreads();
    }
#pragma unroll
    for (int p = 0; p < 4; p++) {
        int o = og * 8 + 2 * p;
        float b0 = bias[o], b1 = bias[o + 1];
#pragma unroll
        for (int j = 0; j < 2; j++) {
            int t = t0 + tA + 32 * j;
            float2 v = up2(acc[p][j]);
            g_h1[((bb * 32) + o) * L1 + t]     = fmaxf(v.x + b0, 0.f);
            g_h1[((bb * 32) + o + 1) * L1 + t] = fmaxf(v.y + b1, 0.f);
        }
    }
}

// ---- conv2: h1->out(16,64,1024), k4 s2 p1, ReLU ----------------------------
__global__ __launch_bounds__(256) void conv2_k(const float* __restrict__ w,
                                               const float* __restrict__ bias,
                                               float* __restrict__ out) {
    extern __shared__ float sm[];
    float* xe = sm;               // [32][68]
    float* xo = sm + 32 * 68;     // [32][68]
    float* ws = xo + 32 * 68;     // [32*4][64]
    const int bb = blockIdx.y, t0 = blockIdx.x * 64;
    const int tid = threadIdx.x, lane = tid & 31, og = tid >> 5;

    u64 acc[4][2];
#pragma unroll
    for (int p = 0; p < 4; p++) { acc[p][0] = 0ull; acc[p][1] = 0ull; }

    for (int i = tid; i < 32 * 4 * 64; i += 256) {
        int k = i & 3, c = (i >> 2) & 31, o = i >> 7;
        ws[(c * 4 + k) * 64 + o] = w[((o * 32) + c) * 4 + k];
    }
    for (int i = tid; i < 32 * 130; i += 256) {
        int c = i / 130, q = i - c * 130;
        int gp = 2 * t0 - 1 + q;
        float v = (gp >= 0 && gp < L1) ? g_h1[((bb * 32) + c) * L1 + gp] : 0.f;
        if (q & 1) xe[c * 68 + (q >> 1)] = v;
        else       xo[c * 68 + (q >> 1)] = v;
    }
    __syncthreads();
#pragma unroll 2
    for (int c = 0; c < 32; ++c) {
        const float* pe = &xe[c * 68];
        const float* po = &xo[c * 68];
        u64 XA[4] = { spl(po[lane]), spl(pe[lane]), spl(po[lane + 1]), spl(pe[lane + 1]) };
        u64 XB[4] = { spl(po[lane + 32]), spl(pe[lane + 32]), spl(po[lane + 33]), spl(pe[lane + 33]) };
        const float* wb = &ws[c * 4 * 64 + og * 8];
#pragma unroll
        for (int k = 0; k < 4; k++) {
#pragma unroll
            for (int p = 0; p < 4; p++) {
                u64 wv = *(const u64*)&wb[k * 64 + 2 * p];
                fma2(acc[p][0], wv, XA[k]);
                fma2(acc[p][1], wv, XB[k]);
            }
        }
    }
#pragma unroll
    for (int p = 0; p < 4; p++) {
        int o = og * 8 + 2 * p;
        float b0 = bias[o], b1 = bias[o + 1];
#pragma unroll
        for (int j = 0; j < 2; j++) {
            int t = t0 + lane + 32 * j;
            float2 v = up2(acc[p][j]);
            out[((bb * 64) + o) * L2 + t]     = fmaxf(v.x + b0, 0.f);
            out[((bb * 64) + o + 1) * L2 + t] = fmaxf(v.y + b1, 0.f);
        }
    }
}

// ---- gconv: 64->64, stride1, pad K/2, +bias --------------------------------
template <int K>
__global__ __launch_bounds__(256) void gconv_k(const float* __restrict__ in,
                                               float* __restrict__ out,
                                               const float* __restrict__ w,
                                               const float* __restrict__ bias) {
    extern __shared__ float sm[];
    constexpr int H = K / 2, W = 64 + 2 * H;
    float* xs = sm;               // [64][68]
    float* ws = sm + 64 * 68;     // [64*K][64]
    const int bb = blockIdx.y, t0 = blockIdx.x * 64;
    const int tid = threadIdx.x, lane = tid & 31, og = tid >> 5;

    u64 acc[4][2];
#pragma unroll
    for (int p = 0; p < 4; p++) { acc[p][0] = 0ull; acc[p][1] = 0ull; }

    for (int i = tid; i < 64 * 64 * K; i += 256) {
        int k = i % K, r = i / K, c = r & 63, o = r >> 6;
        ws[(c * K + k) * 64 + o] = w[(o * 64 + c) * K + k];
    }
    for (int i = tid; i < 64 * W; i += 256) {
        int c = i / W, p = i - c * W;
        int gp = t0 - H + p;
        xs[c * 68 + p] = (gp >= 0 && gp < L2) ? in[((bb * 64) + c) * L2 + gp] : 0.f;
    }
    __syncthreads();
#pragma unroll 2
    for (int c = 0; c < 64; ++c) {
        const float* xr = &xs[c * 68];
        u64 XA[K], XB[K];
#pragma unroll
        for (int k = 0; k < K; k++) { XA[k] = spl(xr[lane + k]); XB[k] = spl(xr[lane + 32 + k]); }
        const float* wb = &ws[c * K * 64 + og * 8];
#pragma unroll
        for (int k = 0; k < K; k++) {
#pragma unroll
            for (int p = 0; p < 4; p++) {
                u64 wv = *(const u64*)&wb[k * 64 + 2 * p];
                fma2(acc[p][0], wv, XA[k]);
                fma2(acc[p][1], wv, XB[k]);
            }
        }
    }
#pragma unroll
    for (int p = 0; p < 4; p++) {
        int o = og * 8 + 2 * p;
        float b0 = bias[o], b1 = bias[o + 1];
#pragma unroll
        for (int j = 0; j < 2; j++) {
            int t = t0 + lane + 32 * j;
            float2 v = up2(acc[p][j]);
            out[((bb * 64) + o) * L2 + t]     = v.x + b0;
            out[((bb * 64) + o + 1) * L2 + t] = v.y + b1;
        }
    }
}

// ---- fused residual block: out = in + conv1x1(relu(conv3(relu(in)))) -------
__global__ __launch_bounds__(256) void res_k(const float* __restrict__ in,
                                             float* __restrict__ out,
                                             const float* __restrict__ w1,
                                             const float* __restrict__ w2,
                                             int relu_out) {
    extern __shared__ float sm[];
    float* xr  = sm;                  // [64][68] relu(in), halo 1
    float* w1s = xr + 64 * 68;        // [64c*3k][32o]
    float* w2s = w1s + 64 * 3 * 32;   // [32c][64o]
    float* hs  = w2s + 32 * 64;       // [32][68] relu(h)
    const int bb = blockIdx.y, t0 = blockIdx.x * 64;
    const int tid = threadIdx.x, lane = tid & 31, og = tid >> 5;

    for (int i = tid; i < 64 * 3 * 32; i += 256) {
        int k = i % 3, r = i / 3, c = r & 63, o = r >> 6;
        w1s[(c * 3 + k) * 32 + o] = w1[(o * 64 + c) * 3 + k];
    }
    for (int i = tid; i < 32 * 64; i += 256) {
        int c = i >> 6, o = i & 63;
        w2s[c * 64 + o] = w2[o * 32 + c];
    }
    for (int i = tid; i < 64 * 66; i += 256) {
        int c = i / 66, p = i - c * 66;
        int gp = t0 - 1 + p;
        float v = (gp >= 0 && gp < L2) ? in[((bb * 64) + c) * L2 + gp] : 0.f;
        xr[c * 68 + p] = fmaxf(v, 0.f);
    }
    __syncthreads();
    // phase 1: h = conv3(relu(in)), 32 channels, relu stored
    {
        u64 a1[2][2];
#pragma unroll
        for (int p = 0; p < 2; p++) { a1[p][0] = 0ull; a1[p][1] = 0ull; }
#pragma unroll 2
        for (int c = 0; c < 64; ++c) {
            const float* xp = &xr[c * 68];
            u64 XA[3], XB[3];
#pragma unroll
            for (int k = 0; k < 3; k++) { XA[k] = spl(xp[lane + k]); XB[k] = spl(xp[lane + 32 + k]); }
            const float* wb = &w1s[c * 3 * 32 + og * 4];
#pragma unroll
            for (int k = 0; k < 3; k++) {
#pragma unroll
                for (int p = 0; p < 2; p++) {
                    u64 wv = *(const u64*)&wb[k * 32 + 2 * p];
                    fma2(a1[p][0], wv, XA[k]);
                    fma2(a1[p][1], wv, XB[k]);
                }
            }
        }
#pragma unroll
        for (int p = 0; p < 2; p++) {
            int o2 = og * 4 + 2 * p;
#pragma unroll
            for (int j = 0; j < 2; j++) {
                float2 v = up2(a1[p][j]);
                hs[o2 * 68 + lane + 32 * j]       = fmaxf(v.x, 0.f);
                hs[(o2 + 1) * 68 + lane + 32 * j] = fmaxf(v.y, 0.f);
            }
        }
    }
    __syncthreads();
    // phase 2: out = in + w2 @ relu(h)
    {
        u64 a2[4][2];
#pragma unroll
        for (int p = 0; p < 4; p++) { a2[p][0] = 0ull; a2[p][1] = 0ull; }
#pragma unroll 4
        for (int c = 0; c < 32; ++c) {
            u64 HA = spl(hs[c * 68 + lane]);
            u64 HB = spl(hs[c * 68 + lane + 32]);
            const float* wb = &w2s[c * 64 + og * 8];
#pragma unroll
            for (int p = 0; p < 4; p++) {
                u64 wv = *(const u64*)&wb[2 * p];
                fma2(a2[p][0], wv, HA);
                fma2(a2[p][1], wv, HB);
            }
        }
#pragma unroll
        for (int p = 0; p < 4; p++) {
            int o = og * 8 + 2 * p;
#pragma unroll
            for (int j = 0; j < 2; j++) {
                int t = t0 + lane + 32 * j;
                float2 v = up2(a2[p][j]);
                float r0 = in[((bb * 64) + o) * L2 + t] + v.x;
                float r1 = in[((bb * 64) + o + 1) * L2 + t] + v.y;
                if (relu_out) { r0 = fmaxf(r0, 0.f); r1 = fmaxf(r1, 0.f); }
                out[((bb * 64) + o) * L2 + t]     = r0;
                out[((bb * 64) + o + 1) * L2 + t] = r1;
            }
        }
    }
}

// ---- codebook squared norms ------------------------------------------------
__global__ void e2_k(const float* __restrict__ emb) {
    int c = blockIdx.x * blockDim.x + threadIdx.x;
    if (c < 512) {
        float s = 0.f;
#pragma unroll 8
        for (int d = 0; d < 64; ++d) { float v = emb[c * 64 + d]; s += v * v; }
        g_e2[c] = s;
    }
}

// ---- VQ: nearest codebook row per (b,t) ------------------------------------
__global__ __launch_bounds__(256) void vq_k(const float* __restrict__ z,
                                            float* __restrict__ q,
                                            const float* __restrict__ emb) {
    extern __shared__ float sm[];
    float* zs  = sm;              // [64][34]
    float* es  = zs + 64 * 34;    // [512][17]
    float* e2s = es + 512 * 17;   // [512]
    __shared__ int idxs[32];
    const int v0 = blockIdx.x * 32;
    const int b = v0 >> 10, t0 = v0 & 1023;
    const int tid = threadIdx.x, lane = tid & 31, vg = tid >> 5;

    for (int i = tid; i < 64 * 32; i += 256) {
        int d = i >> 5, vv = i & 31;
        zs[d * 34 + vv] = z[((b * 64) + d) * L2 + t0 + vv];
    }
    for (int i = tid; i < 512; i += 256) e2s[i] = g_e2[i];

    u64 acc[2][16];
#pragma unroll
    for (int p = 0; p < 2; p++)
#pragma unroll
        for (int j = 0; j < 16; j++) acc[p][j] = 0ull;

    for (int k0 = 0; k0 < 64; k0 += 16) {
        __syncthreads();
        for (int i = tid; i < 512 * 4; i += 256) {
            int c = i >> 2, kq = i & 3;
            float4 v = *(const float4*)&emb[c * 64 + k0 + kq * 4];
            float* d = &es[c * 17 + kq * 4];
            d[0] = v.x; d[1] = v.y; d[2] = v.z; d[3] = v.w;
        }
        __syncthreads();
#pragma unroll
        for (int kd = 0; kd < 16; ++kd) {
            const float* zr = &zs[(k0 + kd) * 34 + vg * 4];
            u64 Z0 = *(const u64*)&zr[0];
            u64 Z1 = *(const u64*)&zr[2];
#pragma unroll
            for (int cc = 0; cc < 16; ++cc) {
                u64 E = spl(es[(lane + 32 * cc) * 17 + kd]);
                fma2(acc[0][cc], Z0, E);
                fma2(acc[1][cc], Z1, E);
            }
        }
    }
#pragma unroll
    for (int vv = 0; vv < 4; ++vv) {
        float mv = 3.0e38f; int mi = 0;
#pragma unroll
        for (int cc = 0; cc < 16; ++cc) {
            int c = lane + 32 * cc;
            float2 pv = up2(acc[vv >> 1][cc]);
            float dot = (vv & 1) ? pv.y : pv.x;
            float val = e2s[c] - 2.0f * dot;
            if (val < mv) { mv = val; mi = c; }
        }
        for (int off = 16; off > 0; off >>= 1) {
            float ov = __shfl_down_sync(0xffffffffu, mv, off);
            int   oi = __shfl_down_sync(0xffffffffu, mi, off);
            if (ov < mv || (ov == mv && oi < mi)) { mv = ov; mi = oi; }
        }
        if (lane == 0) idxs[vg * 4 + vv] = mi;
    }
    __syncthreads();
    for (int i = tid; i < 64 * 32; i += 256) {
        int d = i >> 5, vv = i & 31;
        q[((b * 64) + d) * L2 + t0 + vv] = emb[idxs[vv] * 64 + d];
    }
}

// ---- dect1: ConvTranspose1d 64->32, k4 s2 p1, bias, ReLU -------------------
__global__ __launch_bounds__(256) void dect1_k(const float* __restrict__ in,
                                               const float* __restrict__ w,
                                               const float* __restrict__ bias) {
    extern __shared__ float sm[];
    float* xs = sm;               // [64][68]
    float* ws = sm + 64 * 68;     // [64c*4k][32o]
    const int bb = blockIdx.y, t0 = blockIdx.x * 128;
    const int tid = threadIdx.x, lane = tid & 31, og = tid >> 5;
    const int s0 = t0 / 2 - 1;

    u64 acc[2][4];
#pragma unroll
    for (int p = 0; p < 2; p++)
#pragma unroll
        for (int j = 0; j < 4; j++) acc[p][j] = 0ull;

    for (int i = tid; i < 64 * 32 * 4; i += 256) {
        int k = i & 3, o = (i >> 2) & 31, c = i >> 7;
        ws[(c * 4 + k) * 32 + o] = w[((c * 32) + o) * 4 + k];
    }
    for (int i = tid; i < 64 * 66; i += 256) {
        int c = i / 66, ls = i - c * 66;
        int s = s0 + ls;
        xs[c * 68 + ls] = (s >= 0 && s < L2) ? in[((bb * 64) + c) * L2 + s] : 0.f;
    }
    __syncthreads();
    const int khi = (lane & 1) ? 0 : 1;
    const int klo = khi + 2;
    const int lsb = ((lane + (lane & 1)) >> 1) + 1;
#pragma unroll 2
    for (int c = 0; c < 64; ++c) {
        const float* wbh = &ws[(c * 4 + khi) * 32 + og * 4];
        const float* wbl = &ws[(c * 4 + klo) * 32 + og * 4];
        u64 wh0 = *(const u64*)&wbh[0], wh1 = *(const u64*)&wbh[2];
        u64 wl0 = *(const u64*)&wbl[0], wl1 = *(const u64*)&wbl[2];
#pragma unroll
        for (int tj = 0; tj < 4; tj++) {
            int lh = lsb + 16 * tj;
            u64 XH = spl(xs[c * 68 + lh]);
            u64 XL = spl(xs[c * 68 + lh - 1]);
            fma2(acc[0][tj], wh0, XH); fma2(acc[0][tj], wl0, XL);
            fma2(acc[1][tj], wh1, XH); fma2(acc[1][tj], wl1, XL);
        }
    }
#pragma unroll
    for (int p = 0; p < 2; p++) {
        int o = og * 4 + 2 * p;
        float b0 = bias[o], b1 = bias[o + 1];
#pragma unroll
        for (int tj = 0; tj < 4; tj++) {
            int t = t0 + lane + 32 * tj;
            float2 v = up2(acc[p][tj]);
            g_d1[((bb * 32) + o) * L1 + t]     = fmaxf(v.x + b0, 0.f);
            g_d1[((bb * 32) + o + 1) * L1 + t] = fmaxf(v.y + b1, 0.f);
        }
    }
}

// ---- dect2: ConvTranspose1d 32->64, k4 s2 p1, bias -> d_out ----------------
__global__ __launch_bounds__(256) void dect2_k(const float* __restrict__ w,
                                               const float* __restrict__ bias,
                                               float* __restrict__ out) {
    extern __shared__ float sm[];
    float* xs = sm;               // [32][36]
    float* ws = sm + 32 * 36;     // [32c*4k][64o]
    const int bb = blockIdx.y, t0 = blockIdx.x * 64;
    const int tid = threadIdx.x, lane = tid & 31, og = tid >> 5;
    const int s0 = t0 / 2 - 1;

    u64 acc[4][2];
#pragma unroll
    for (int p = 0; p < 4; p++) { acc[p][0] = 0ull; acc[p][1] = 0ull; }

    for (int i = tid; i < 32 * 64 * 4; i += 256) {
        int k = i & 3, o = (i >> 2) & 63, c = i >> 8;
        ws[(c * 4 + k) * 64 + o] = w[((c * 64) + o) * 4 + k];
    }
    for (int i = tid; i < 32 * 34; i += 256) {
        int c = i / 34, ls = i - c * 34;
        int s = s0 + ls;
        xs[c * 36 + ls] = (s >= 0 && s < L1) ? g_d1[((bb * 32) + c) * L1 + s] : 0.f;
    }
    __syncthreads();
    const int khi = (lane & 1) ? 0 : 1;
    const int klo = khi + 2;
    const int lsb = ((lane + (lane & 1)) >> 1) + 1;
#pragma unroll 2
    for (int c = 0; c < 32; ++c) {
        const float* wbh = &ws[(c * 4 + khi) * 64 + og * 8];
        const float* wbl = &ws[(c * 4 + klo) * 64 + og * 8];
#pragma unroll
        for (int tj = 0; tj < 2; tj++) {
            int lh = lsb + 16 * tj;
            u64 XH = spl(xs[c * 36 + lh]);
            u64 XL = spl(xs[c * 36 + lh - 1]);
#pragma unroll
            for (int p = 0; p < 4; p++) {
                u64 wh = *(const u64*)&wbh[2 * p];
                u64 wl = *(const u64*)&wbl[2 * p];
                fma2(acc[p][tj], wh, XH);
                fma2(acc[p][tj], wl, XL);
            }
        }
    }
#pragma unroll
    for (int p = 0; p < 4; p++) {
        int o = og * 8 + 2 * p;
        float b0 = bias[o], b1 = bias[o + 1];
#pragma unroll
        for (int tj = 0; tj < 2; tj++) {
            int t = t0 + lane + 32 * tj;
            float2 v = up2(acc[p][tj]);
            out[((bb * 64) + o) * L0 + t]     = v.x + b0;
            out[((bb * 64) + o + 1) * L0 + t] = v.y + b1;
        }
    }
}

extern "C" void kernel_launch(void* const* d_in, const int* in_sizes, int n_in,
                              void* d_out, int out_size) {
    const float* x         = (const float*)d_in[0];
    const float* enc_w1    = (const float*)d_in[1];
    const float* enc_b1    = (const float*)d_in[2];
    const float* enc_w2    = (const float*)d_in[3];
    const float* enc_b2    = (const float*)d_in[4];
    const float* enc_w3    = (const float*)d_in[5];
    const float* enc_b3    = (const float*)d_in[6];
    const float* enc_r0_w1 = (const float*)d_in[7];
    const float* enc_r0_w2 = (const float*)d_in[8];
    const float* enc_r1_w1 = (const float*)d_in[9];
    const float* enc_r1_w2 = (const float*)d_in[10];
    const float* prevq_w   = (const float*)d_in[11];
    const float* prevq_b   = (const float*)d_in[12];
    const float* emb       = (const float*)d_in[13];
    const float* dec_w1    = (const float*)d_in[14];
    const float* dec_b1    = (const float*)d_in[15];
    const float* dec_r0_w1 = (const float*)d_in[16];
    const float* dec_r0_w2 = (const float*)d_in[17];
    const float* dec_r1_w1 = (const float*)d_in[18];
    const float* dec_r1_w2 = (const float*)d_in[19];
    const float* dect1_w   = (const float*)d_in[20];
    const float* dect1_b   = (const float*)d_in[21];
    const float* dect2_w   = (const float*)d_in[22];
    const float* dect2_b   = (const float*)d_in[23];
    float* out = (float*)d_out;

    float *A, *B, *C;
    cudaGetSymbolAddress((void**)&A, g_A);
    cudaGetSymbolAddress((void**)&B, g_B);
    cudaGetSymbolAddress((void**)&C, g_C);

    cudaFuncSetAttribute(conv1_k, cudaFuncAttributeMaxDynamicSharedMemorySize, 65536);
    cudaFuncSetAttribute(conv2_k, cudaFuncAttributeMaxDynamicSharedMemorySize, 65536);
    cudaFuncSetAttribute(gconv_k<3>, cudaFuncAttributeMaxDynamicSharedMemorySize, 98304);
    cudaFuncSetAttribute(res_k, cudaFuncAttributeMaxDynamicSharedMemorySize, 65536);
    cudaFuncSetAttribute(dect1_k, cudaFuncAttributeMaxDynamicSharedMemorySize, 65536);

    dim3 blk(256);
    size_t sm_c1  = (32 * 132 * 2 + 32 * 4 * 32) * 4;
    size_t sm_c2  = (32 * 68 * 2 + 32 * 4 * 64) * 4;
    size_t sm_g3  = (64 * 68 + 64 * 3 * 64) * 4;
    size_t sm_g1  = (64 * 68 + 64 * 64) * 4;
    size_t sm_res = (64 * 68 + 64 * 3 * 32 + 32 * 64 + 32 * 68) * 4;
    size_t sm_vq  = (64 * 34 + 512 * 17 + 512) * 4;
    size_t sm_d1  = (64 * 68 + 64 * 4 * 32) * 4;
    size_t sm_d2  = (32 * 36 + 32 * 4 * 64) * 4;
    dim3 gg(L2 / 64, BATCH);

    // encoder
    conv1_k<<<dim3(L1 / 128, BATCH), blk, sm_c1>>>(x, enc_w1, enc_b1);
    conv2_k<<<gg, blk, sm_c2>>>(enc_w2, enc_b2, A);
    gconv_k<3><<<gg, blk, sm_g3>>>(A, B, enc_w3, enc_b3);
    res_k<<<gg, blk, sm_res>>>(B, A, enc_r0_w1, enc_r0_w2, 0);
    res_k<<<gg, blk, sm_res>>>(A, B, enc_r1_w1, enc_r1_w2, 1);
    gconv_k<1><<<gg, blk, sm_g1>>>(B, A, prevq_w, prevq_b);
    // VQ
    e2_k<<<2, 256>>>(emb);
    vq_k<<<BATCH * L2 / 32, blk, sm_vq>>>(A, C, emb);
    // decoder
    gconv_k<3><<<gg, blk, sm_g3>>>(C, A, dec_w1, dec_b1);
    res_k<<<gg, blk, sm_res>>>(A, B, dec_r0_w1, dec_r0_w2, 0);
    res_k<<<gg, blk, sm_res>>>(B, A, dec_r1_w1, dec_r1_w2, 1);
    dect1_k<<<dim3(L1 / 128, BATCH), blk, sm_d1>>>(A, dect1_w, dect1_b);
    dect2_k<<<dim3(L0 / 64, BATCH), blk, sm_d2>>>(dect2_w, dect2_b, out);
}

// round 11
// speedup vs baseline: 1.0011x; 1.0011x over previous
#include <cuda_runtime.h>

#define BATCH 16
#define CIN   768
#define L0    4096
#define L1    2048
#define L2    1024

__device__ float g_h1[BATCH * 32 * L1];
__device__ float g_A[BATCH * 64 * L2];
__device__ float g_B[BATCH * 64 * L2];
__device__ float g_C[BATCH * 64 * L2];
__device__ float g_d1[BATCH * 32 * L1];
__device__ float g_e2[512];

__device__ __forceinline__ float tf32r(float v) {
    unsigned r; asm("cvt.rna.tf32.f32 %0,%1;" : "=r"(r) : "f"(v));
    return __uint_as_float(r);
}
__device__ __forceinline__ void mma8(float* d, float4 A, unsigned b0, unsigned b1) {
    unsigned a0 = __float_as_uint(A.x), a1 = __float_as_uint(A.y);
    unsigned a2 = __float_as_uint(A.z), a3 = __float_as_uint(A.w);
    asm volatile(
        "mma.sync.aligned.m16n8k8.row.col.f32.tf32.tf32.f32 "
        "{%0,%1,%2,%3},{%4,%5,%6,%7},{%8,%9},{%0,%1,%2,%3};"
        : "+f"(d[0]), "+f"(d[1]), "+f"(d[2]), "+f"(d[3])
        : "r"(a0), "r"(a1), "r"(a2), "r"(a3), "r"(b0), "r"(b1));
}

// ---- conv1 (tensor cores, 3xTF32): x(16,768,4096)->h1(16,32,2048) ----------
// GEMM: M=32 out-ch (2 m16 tiles), N=64 positions/block (8 warps x n8), K=3072.
__global__ __launch_bounds__(256) void conv1_tc(const float* __restrict__ x,
                                                const float* __restrict__ w,
                                                const float* __restrict__ bias) {
    extern __shared__ float sm[];
    float* Ah = sm;                  // [16s][2ct][32l][4] = 4096
    float* Al = Ah + 4096;
    float* xh = Al + 4096;           // [32c][132]
    float* xl = xh + 32 * 132;
    const int bb = blockIdx.y, t0 = blockIdx.x * 64;
    const int tid = threadIdx.x, lane = tid & 31, pt = tid >> 5;

    float acc[2][4];
#pragma unroll
    for (int ct = 0; ct < 2; ct++)
#pragma unroll
        for (int j = 0; j < 4; j++) acc[ct][j] = 0.f;

    const int pbase = 2 * (pt * 8 + (lane >> 2)) + (lane & 3);

    for (int c0 = 0; c0 < CIN; c0 += 32) {
        // weights -> fragment-permuted smem (hi/lo split)
        for (int i = tid; i < 4096; i += 256) {
            int j = i & 3, l = (i >> 2) & 31, ct = (i >> 7) & 1, s = i >> 8;
            int o   = ct * 16 + (l >> 2) + (j & 1) * 8;
            int col = (l & 3) + (j >> 1) * 4;
            int cl  = 2 * s + (col >> 2), kk = col & 3;
            float v = w[(o * CIN + c0 + cl) * 4 + kk];
            float h = tf32r(v);
            Ah[i] = h; Al[i] = tf32r(v - h);
        }
        // x slice -> smem (hi/lo split), p=0..129 <-> x[2t0-1+p]
        for (int i = tid; i < 32 * 130; i += 256) {
            int c = i / 130, p = i - c * 130;
            int gp = 2 * t0 - 1 + p;
            float v = (gp >= 0 && gp < L0) ? x[((bb * CIN) + c0 + c) * L0 + gp] : 0.f;
            float h = tf32r(v);
            xh[c * 132 + p] = h; xl[c * 132 + p] = tf32r(v - h);
        }
        __syncthreads();
#pragma unroll
        for (int s = 0; s < 16; s++) {
            unsigned bh0 = __float_as_uint(xh[(2 * s) * 132 + pbase]);
            unsigned bh1 = __float_as_uint(xh[(2 * s + 1) * 132 + pbase]);
            unsigned bl0 = __float_as_uint(xl[(2 * s) * 132 + pbase]);
            unsigned bl1 = __float_as_uint(xl[(2 * s + 1) * 132 + pbase]);
#pragma unroll
            for (int ct = 0; ct < 2; ct++) {
                float4 AH = ((const float4*)Ah)[(s * 2 + ct) * 32 + lane];
                float4 AL = ((const float4*)Al)[(s * 2 + ct) * 32 + lane];
                mma8(acc[ct], AH, bh0, bh1);
                mma8(acc[ct], AH, bl0, bl1);
                mma8(acc[ct], AL, bh0, bh1);
            }
        }
        __syncthreads();
    }
    const int gr = lane >> 2, nb = pt * 8 + 2 * (lane & 3);
#pragma unroll
    for (int ct = 0; ct < 2; ct++) {
        int o0 = ct * 16 + gr, o1 = o0 + 8;
        float b0 = bias[o0], b1 = bias[o1];
        int t = t0 + nb;
        g_h1[(bb * 32 + o0) * L1 + t]     = fmaxf(acc[ct][0] + b0, 0.f);
        g_h1[(bb * 32 + o0) * L1 + t + 1] = fmaxf(acc[ct][1] + b0, 0.f);
        g_h1[(bb * 32 + o1) * L1 + t]     = fmaxf(acc[ct][2] + b1, 0.f);
        g_h1[(bb * 32 + o1) * L1 + t + 1] = fmaxf(acc[ct][3] + b1, 0.f);
    }
}

// ---- conv2: h1->out(16,64,1024), k4 s2 p1, ReLU (scalar, R5 form) ----------
__global__ __launch_bounds__(256) void conv2_k(const float* __restrict__ w,
                                               const float* __restrict__ bias,
                                               float* __restrict__ out) {
    extern __shared__ float sm[];
    float* xs = sm;               // [32][132]
    float* ws = sm + 32 * 132;    // [32*4][68]
    const int b = blockIdx.y, t0 = blockIdx.x * 64;
    const int tid = threadIdx.x, lane = tid & 31, og = tid >> 5;
    float acc[8][2];
#pragma unroll
    for (int i = 0; i < 8; i++) { acc[i][0] = 0.f; acc[i][1] = 0.f; }

    for (int i = tid; i < 64 * 32 * 4; i += 256) {
        int k = i & 3, c = (i >> 2) & 31, o = i >> 7;
        ws[(c * 4 + k) * 68 + o] = w[((o * 32) + c) * 4 + k];
    }
    for (int i = tid; i < 32 * 130; i += 256) {
        int c = i / 130, p = i - c * 130;
        int gp = 2 * t0 - 1 + p;
        xs[c * 132 + p] = (gp >= 0 && gp < L1) ? g_h1[((b * 32) + c) * L1 + gp] : 0.f;
    }
    __syncthreads();
#pragma unroll 4
    for (int c = 0; c < 32; ++c) {
        float wr[4][8];
#pragma unroll
        for (int k = 0; k < 4; k++) {
            float4 a  = *(const float4*)&ws[(c * 4 + k) * 68 + og * 8];
            float4 b4 = *(const float4*)&ws[(c * 4 + k) * 68 + og * 8 + 4];
            wr[k][0] = a.x;  wr[k][1] = a.y;  wr[k][2] = a.z;  wr[k][3] = a.w;
            wr[k][4] = b4.x; wr[k][5] = b4.y; wr[k][6] = b4.z; wr[k][7] = b4.w;
        }
#pragma unroll
        for (int tj = 0; tj < 2; tj++) {
            const float* xr = &xs[c * 132 + 2 * (lane + 32 * tj)];
            float x0 = xr[0], x1 = xr[1], x2 = xr[2], x3 = xr[3];
#pragma unroll
            for (int oi = 0; oi < 8; oi++)
                acc[oi][tj] += wr[0][oi] * x0 + wr[1][oi] * x1 + wr[2][oi] * x2 + wr[3][oi] * x3;
        }
    }
#pragma unroll
    for (int oi = 0; oi < 8; oi++) {
        int o = og * 8 + oi;
        float bv = bias[o];
#pragma unroll
        for (int tj = 0; tj < 2; tj++)
            out[((b * 64) + o) * L2 + t0 + lane + 32 * tj] = fmaxf(acc[oi][tj] + bv, 0.f);
    }
}

// ---- generic conv 64->64, stride1, pad K/2 (scalar, R5 form) ---------------
template <int K>
__global__ __launch_bounds__(256) void gconv_k(const float* __restrict__ in,
                                               float* __restrict__ out,
                                               const float* __restrict__ w,
                                               const float* __restrict__ bias) {
    extern __shared__ float sm[];
    constexpr int H = K / 2, W = 64 + 2 * H;
    float* xs = sm;               // [64][68]
    float* ws = sm + 64 * 68;     // [64*K][68]
    const int b = blockIdx.y, t0 = blockIdx.x * 64;
    const int tid = threadIdx.x, lane = tid & 31, og = tid >> 5;
    float acc[8][2];
#pragma unroll
    for (int i = 0; i < 8; i++) { acc[i][0] = 0.f; acc[i][1] = 0.f; }

    for (int i = tid; i < 64 * 64 * K; i += 256) {
        int k = i % K, r = i / K, c = r & 63, o = r >> 6;
        ws[(c * K + k) * 68 + o] = w[(o * 64 + c) * K + k];
    }
    for (int i = tid; i < 64 * W; i += 256) {
        int c = i / W, p = i - c * W;
        int gp = t0 - H + p;
        xs[c * 68 + p] = (gp >= 0 && gp < L2) ? in[((b * 64) + c) * L2 + gp] : 0.f;
    }
    __syncthreads();
#pragma unroll 2
    for (int c = 0; c < 64; ++c) {
        float wr[K][8];
#pragma unroll
        for (int k = 0; k < K; k++) {
            float4 a  = *(const float4*)&ws[(c * K + k) * 68 + og * 8];
            float4 b4 = *(const float4*)&ws[(c * K + k) * 68 + og * 8 + 4];
            wr[k][0] = a.x;  wr[k][1] = a.y;  wr[k][2] = a.z;  wr[k][3] = a.w;
            wr[k][4] = b4.x; wr[k][5] = b4.y; wr[k][6] = b4.z; wr[k][7] = b4.w;
        }
#pragma unroll
        for (int tj = 0; tj < 2; tj++) {
            const float* xr = &xs[c * 68 + lane + 32 * tj];
#pragma unroll
            for (int oi = 0; oi < 8; oi++) {
                float s = 0.f;
#pragma unroll
                for (int k = 0; k < K; k++) s += wr[k][oi] * xr[k];
                acc[oi][tj] += s;
            }
        }
    }
#pragma unroll
    for (int oi = 0; oi < 8; oi++) {
        int o = og * 8 + oi;
        float bv = bias[o];
#pragma unroll
        for (int tj = 0; tj < 2; tj++)
            out[((b * 64) + o) * L2 + t0 + lane + 32 * tj] = acc[oi][tj] + bv;
    }
}

// ---- fused residual block (scalar): out = in + w2 @ relu(conv3(relu(in))) --
__global__ __launch_bounds__(256) void res_k(const float* __restrict__ in,
                                             float* __restrict__ out,
                                             const float* __restrict__ w1,
                                             const float* __restrict__ w2,
                                             int relu_out) {
    extern __shared__ float sm[];
    float* xr  = sm;                  // [64][68] relu(in) with halo 1
    float* w1s = xr + 64 * 68;        // [64c*3k][36]
    float* w2s = w1s + 64 * 3 * 36;   // [32c][68]
    float* hs  = w2s + 32 * 68;       // [32][66]
    const int bb = blockIdx.y, t0 = blockIdx.x * 64;
    const int tid = threadIdx.x, lane = tid & 31, og = tid >> 5;

    for (int i = tid; i < 64 * 3 * 32; i += 256) {
        int k = i % 3, r = i / 3, c = r & 63, o = r >> 6;
        w1s[(c * 3 + k) * 36 + o] = w1[(o * 64 + c) * 3 + k];
    }
    for (int i = tid; i < 32 * 64; i += 256) {
        int c = i >> 6, o = i & 63;
        w2s[c * 68 + o] = w2[o * 32 + c];
    }
    for (int i = tid; i < 64 * 66; i += 256) {
        int c = i / 66, p = i - c * 66;
        int gp = t0 - 1 + p;
        float v = (gp >= 0 && gp < L2) ? in[((bb * 64) + c) * L2 + gp] : 0.f;
        xr[c * 68 + p] = fmaxf(v, 0.f);
    }
    __syncthreads();
    {   // phase 1: h = relu(conv3(relu(in))), 32 mid channels
        float a1[4][2];
#pragma unroll
        for (int i = 0; i < 4; i++) { a1[i][0] = 0.f; a1[i][1] = 0.f; }
#pragma unroll 2
        for (int c = 0; c < 64; ++c) {
            float wr[3][4];
#pragma unroll
            for (int k = 0; k < 3; k++) {
                float4 a = *(const float4*)&w1s[(c * 3 + k) * 36 + og * 4];
                wr[k][0] = a.x; wr[k][1] = a.y; wr[k][2] = a.z; wr[k][3] = a.w;
            }
#pragma unroll
            for (int tj = 0; tj < 2; tj++) {
                const float* xp = &xr[c * 68 + lane + 32 * tj];
                float x0 = xp[0], x1 = xp[1], x2 = xp[2];
#pragma unroll
                for (int oi = 0; oi < 4; oi++)
                    a1[oi][tj] += wr[0][oi] * x0 + wr[1][oi] * x1 + wr[2][oi] * x2;
            }
        }
#pragma unroll
        for (int oi = 0; oi < 4; oi++)
#pragma unroll
            for (int tj = 0; tj < 2; tj++)
                hs[(og * 4 + oi) * 66 + lane + 32 * tj] = fmaxf(a1[oi][tj], 0.f);
    }
    __syncthreads();
    {   // phase 2: out = in + w2 @ h
        float a2[8][2];
#pragma unroll
        for (int i = 0; i < 8; i++) { a2[i][0] = 0.f; a2[i][1] = 0.f; }
#pragma unroll 4
        for (int c = 0; c < 32; ++c) {
            float4 a  = *(const float4*)&w2s[c * 68 + og * 8];
            float4 b4 = *(const float4*)&w2s[c * 68 + og * 8 + 4];
            float wr[8] = {a.x, a.y, a.z, a.w, b4.x, b4.y, b4.z, b4.w};
#pragma unroll
            for (int tj = 0; tj < 2; tj++) {
                float hv = hs[c * 66 + lane + 32 * tj];
#pragma unroll
                for (int oi = 0; oi < 8; oi++) a2[oi][tj] += wr[oi] * hv;
            }
        }
#pragma unroll
        for (int oi = 0; oi < 8; oi++) {
            int o = og * 8 + oi;
#pragma unroll
            for (int tj = 0; tj < 2; tj++) {
                int t = t0 + lane + 32 * tj;
                float v = in[((bb * 64) + o) * L2 + t] + a2[oi][tj];
                if (relu_out) v = fmaxf(v, 0.f);
                out[((bb * 64) + o) * L2 + t] = v;
            }
        }
    }
}

// ---- codebook squared norms ------------------------------------------------
__global__ void e2_k(const float* __restrict__ emb) {
    int c = blockIdx.x * blockDim.x + threadIdx.x;
    if (c < 512) {
        float s = 0.f;
#pragma unroll 8
        for (int d = 0; d < 64; ++d) { float v = emb[c * 64 + d]; s += v * v; }
        g_e2[c] = s;
    }
}

// ---- VQ: nearest codebook row per (b,t) (scalar, R5 form) ------------------
__global__ __launch_bounds__(256) void vq_k(const float* __restrict__ z,
                                            float* __restrict__ q,
                                            const float* __restrict__ emb) {
    extern __shared__ float sm[];
    float* zs  = sm;              // [64][33]
    float* es  = zs + 64 * 33;    // [512][17]
    float* e2s = es + 512 * 17;   // [512]
    __shared__ int idxs[32];
    const int v0 = blockIdx.x * 32;
    const int b = v0 >> 10, t0 = v0 & 1023;
    const int tid = threadIdx.x, lane = tid & 31, vg = tid >> 5;

    for (int i = tid; i < 64 * 32; i += 256) {
        int d = i >> 5, vv = i & 31;
        zs[d * 33 + vv] = z[((b * 64) + d) * L2 + t0 + vv];
    }
    for (int i = tid; i < 512; i += 256) e2s[i] = g_e2[i];

    float acc[4][16];
#pragma unroll
    for (int i = 0; i < 4; i++)
#pragma unroll
        for (int j = 0; j < 16; j++) acc[i][j] = 0.f;

    for (int k0 = 0; k0 < 64; k0 += 16) {
        __syncthreads();
        for (int i = tid; i < 512 * 4; i += 256) {
            int c = i >> 2, kq = i & 3;
            float4 v = *(const float4*)&emb[c * 64 + k0 + kq * 4];
            float* d = &es[c * 17 + kq * 4];
            d[0] = v.x; d[1] = v.y; d[2] = v.z; d[3] = v.w;
        }
        __syncthreads();
#pragma unroll
        for (int kd = 0; kd < 16; ++kd) {
            float zv0 = zs[(k0 + kd) * 33 + vg * 4 + 0];
            float zv1 = zs[(k0 + kd) * 33 + vg * 4 + 1];
            float zv2 = zs[(k0 + kd) * 33 + vg * 4 + 2];
            float zv3 = zs[(k0 + kd) * 33 + vg * 4 + 3];
#pragma unroll
            for (int cc = 0; cc < 16; ++cc) {
                float ev = es[(lane + 32 * cc) * 17 + kd];
                acc[0][cc] += zv0 * ev;
                acc[1][cc] += zv1 * ev;
                acc[2][cc] += zv2 * ev;
                acc[3][cc] += zv3 * ev;
            }
        }
    }
#pragma unroll
    for (int vv = 0; vv < 4; ++vv) {
        float mv = 3.0e38f; int mi = 0;
#pragma unroll
        for (int cc = 0; cc < 16; ++cc) {
            int c = lane + 32 * cc;
            float val = e2s[c] - 2.0f * acc[vv][cc];
            if (val < mv) { mv = val; mi = c; }
        }
        for (int off = 16; off > 0; off >>= 1) {
            float ov = __shfl_down_sync(0xffffffffu, mv, off);
            int   oi = __shfl_down_sync(0xffffffffu, mi, off);
            if (ov < mv || (ov == mv && oi < mi)) { mv = ov; mi = oi; }
        }
        if (lane == 0) idxs[vg * 4 + vv] = mi;
    }
    __syncthreads();
    for (int i = tid; i < 64 * 32; i += 256) {
        int d = i >> 5, vv = i & 31;
        q[((b * 64) + d) * L2 + t0 + vv] = emb[idxs[vv] * 64 + d];
    }
}

// ---- dect1: ConvTranspose1d 64->32, k4 s2 p1, bias, ReLU (R5 form) ---------
__global__ __launch_bounds__(256) void dect1_k(const float* __restrict__ in,
                                               const float* __restrict__ w,
                                               const float* __restrict__ bias) {
    extern __shared__ float sm[];
    float* xs = sm;               // [64][68]
    float* ws = sm + 64 * 68;     // [64c*4k][36]
    const int b = blockIdx.y, t0 = blockIdx.x * 128;
    const int tid = threadIdx.x, lane = tid & 31, og = tid >> 5;
    const int s0 = t0 / 2 - 1;
    float acc[4][4];
#pragma unroll
    for (int i = 0; i < 4; i++)
#pragma unroll
        for (int j = 0; j < 4; j++) acc[i][j] = 0.f;

    for (int i = tid; i < 64 * 32 * 4; i += 256) {
        int k = i & 3, o = (i >> 2) & 31, c = i >> 7;
        ws[(c * 4 + k) * 36 + o] = w[((c * 32) + o) * 4 + k];
    }
    for (int i = tid; i < 64 * 66; i += 256) {
        int c = i / 66, ls = i - c * 66;
        int s = s0 + ls;
        xs[c * 68 + ls] = (s >= 0 && s < L2) ? in[((b * 64) + c) * L2 + s] : 0.f;
    }
    __syncthreads();
    const int khi = (lane & 1) ? 0 : 1;
    const int klo = khi + 2;
    const int lsb = ((lane + (lane & 1)) >> 1) + 1;
#pragma unroll 2
    for (int c = 0; c < 64; ++c) {
        float4 wh = *(const float4*)&ws[(c * 4 + khi) * 36 + og * 4];
        float4 wl = *(const float4*)&ws[(c * 4 + klo) * 36 + og * 4];
#pragma unroll
        for (int tj = 0; tj < 4; tj++) {
            int lh = lsb + 16 * tj;
            float xh = xs[c * 68 + lh], xl = xs[c * 68 + lh - 1];
            acc[0][tj] += wh.x * xh + wl.x * xl;
            acc[1][tj] += wh.y * xh + wl.y * xl;
            acc[2][tj] += wh.z * xh + wl.z * xl;
            acc[3][tj] += wh.w * xh + wl.w * xl;
        }
    }
#pragma unroll
    for (int oi = 0; oi < 4; oi++) {
        int o = og * 4 + oi;
        float bv = bias[o];
#pragma unroll
        for (int tj = 0; tj < 4; tj++)
            g_d1[((b * 32) + o) * L1 + t0 + lane + 32 * tj] = fmaxf(acc[oi][tj] + bv, 0.f);
    }
}

// ---- dect2: ConvTranspose1d 32->64, k4 s2 p1, bias -> d_out (R5 form) ------
__global__ __launch_bounds__(256) void dect2_k(const float* __restrict__ w,
                                               const float* __restrict__ bias,
                                               float* __restrict__ out) {
    extern __shared__ float sm[];
    float* xs = sm;               // [32][68]
    float* ws = sm + 32 * 68;     // [32c*4k][68]
    const int b = blockIdx.y, t0 = blockIdx.x * 128;
    const int tid = threadIdx.x, lane = tid & 31, og = tid >> 5;
    const int s0 = t0 / 2 - 1;
    float acc[8][4];
#pragma unroll
    for (int i = 0; i < 8; i++)
#pragma unroll
        for (int j = 0; j < 4; j++) acc[i][j] = 0.f;

    for (int i = tid; i < 32 * 64 * 4; i += 256) {
        int k = i & 3, o = (i >> 2) & 63, c = i >> 8;
        ws[(c * 4 + k) * 68 + o] = w[((c * 64) + o) * 4 + k];
    }
    for (int i = tid; i < 32 * 66; i += 256) {
        int c = i / 66, ls = i - c * 66;
        int s = s0 + ls;
        xs[c * 68 + ls] = (s >= 0 && s < L1) ? g_d1[((b * 32) + c) * L1 + s] : 0.f;
    }
    __syncthreads();
    const int khi = (lane & 1) ? 0 : 1;
    const int klo = khi + 2;
    const int lsb = ((lane + (lane & 1)) >> 1) + 1;
#pragma unroll 2
    for (int c = 0; c < 32; ++c) {
        float4 wh0 = *(const float4*)&ws[(c * 4 + khi) * 68 + og * 8];
        float4 wh1 = *(const float4*)&ws[(c * 4 + khi) * 68 + og * 8 + 4];
        float4 wl0 = *(const float4*)&ws[(c * 4 + klo) * 68 + og * 8];
        float4 wl1 = *(const float4*)&ws[(c * 4 + klo) * 68 + og * 8 + 4];
        float wh[8] = {wh0.x, wh0.y, wh0.z, wh0.w, wh1.x, wh1.y, wh1.z, wh1.w};
        float wl[8] = {wl0.x, wl0.y, wl0.z, wl0.w, wl1.x, wl1.y, wl1.z, wl1.w};
#pragma unroll
        for (int tj = 0; tj < 4; tj++) {
            int lh = lsb + 16 * tj;
            float xh = xs[c * 68 + lh], xl = xs[c * 68 + lh - 1];
#pragma unroll
            for (int oi = 0; oi < 8; oi++)
                acc[oi][tj] += wh[oi] * xh + wl[oi] * xl;
        }
    }
#pragma unroll
    for (int oi = 0; oi < 8; oi++) {
        int o = og * 8 + oi;
        float bv = bias[o];
#pragma unroll
        for (int tj = 0; tj < 4; tj++)
            out[((b * 64) + o) * L0 + t0 + lane + 32 * tj] = acc[oi][tj] + bv;
    }
}

extern "C" void kernel_launch(void* const* d_in, const int* in_sizes, int n_in,
                              void* d_out, int out_size) {
    const float* x         = (const float*)d_in[0];
    const float* enc_w1    = (const float*)d_in[1];
    const float* enc_b1    = (const float*)d_in[2];
    const float* enc_w2    = (const float*)d_in[3];
    const float* enc_b2    = (const float*)d_in[4];
    const float* enc_w3    = (const float*)d_in[5];
    const float* enc_b3    = (const float*)d_in[6];
    const float* enc_r0_w1 = (const float*)d_in[7];
    const float* enc_r0_w2 = (const float*)d_in[8];
    const float* enc_r1_w1 = (const float*)d_in[9];
    const float* enc_r1_w2 = (const float*)d_in[10];
    const float* prevq_w   = (const float*)d_in[11];
    const float* prevq_b   = (const float*)d_in[12];
    const float* emb       = (const float*)d_in[13];
    const float* dec_w1    = (const float*)d_in[14];
    const float* dec_b1    = (const float*)d_in[15];
    const float* dec_r0_w1 = (const float*)d_in[16];
    const float* dec_r0_w2 = (const float*)d_in[17];
    const float* dec_r1_w1 = (const float*)d_in[18];
    const float* dec_r1_w2 = (const float*)d_in[19];
    const float* dect1_w   = (const float*)d_in[20];
    const float* dect1_b   = (const float*)d_in[21];
    const float* dect2_w   = (const float*)d_in[22];
    const float* dect2_b   = (const float*)d_in[23];
    float* out = (float*)d_out;

    float *A, *B, *C;
    cudaGetSymbolAddress((void**)&A, g_A);
    cudaGetSymbolAddress((void**)&B, g_B);
    cudaGetSymbolAddress((void**)&C, g_C);

    cudaFuncSetAttribute(conv1_tc, cudaFuncAttributeMaxDynamicSharedMemorySize, 98304);
    cudaFuncSetAttribute(conv2_k, cudaFuncAttributeMaxDynamicSharedMemorySize, 65536);
    cudaFuncSetAttribute(gconv_k<3>, cudaFuncAttributeMaxDynamicSharedMemorySize, 98304);
    cudaFuncSetAttribute(res_k, cudaFuncAttributeMaxDynamicSharedMemorySize, 65536);
    cudaFuncSetAttribute(dect1_k, cudaFuncAttributeMaxDynamicSharedMemorySize, 65536);

    dim3 blk(256);
    size_t sm_c1  = (4096 * 2 + 32 * 132 * 2) * 4;
    size_t sm_c2  = (32 * 132 + 128 * 68) * 4;
    size_t sm_g3  = (64 * 68 + 64 * 3 * 68) * 4;
    size_t sm_g1  = (64 * 68 + 64 * 68) * 4;
    size_t sm_res = (64 * 68 + 64 * 3 * 36 + 32 * 68 + 32 * 66) * 4;
    size_t sm_vq  = (64 * 33 + 512 * 17 + 512) * 4;
    size_t sm_d1  = (64 * 68 + 256 * 36) * 4;
    size_t sm_d2  = (32 * 68 + 128 * 68) * 4;
    dim3 gg(L2 / 64, BATCH);

    // encoder
    conv1_tc<<<dim3(L1 / 64, BATCH), blk, sm_c1>>>(x, enc_w1, enc_b1);
    conv2_k<<<gg, blk, sm_c2>>>(enc_w2, enc_b2, A);
    gconv_k<3><<<gg, blk, sm_g3>>>(A, B, enc_w3, enc_b3);
    res_k<<<gg, blk, sm_res>>>(B, A, enc_r0_w1, enc_r0_w2, 0);
    res_k<<<gg, blk, sm_res>>>(A, B, enc_r1_w1, enc_r1_w2, 1);
    gconv_k<1><<<gg, blk, sm_g1>>>(B, A, prevq_w, prevq_b);
    // VQ
    e2_k<<<2, 256>>>(emb);
    vq_k<<<BATCH * L2 / 32, blk, sm_vq>>>(A, C, emb);
    // decoder
    gconv_k<3><<<gg, blk, sm_g3>>>(C, A, dec_w1, dec_b1);
    res_k<<<gg, blk, sm_res>>>(A, B, dec_r0_w1, dec_r0_w2, 0);
    res_k<<<gg, blk, sm_res>>>(B, A, dec_r1_w1, dec_r1_w2, 1);
    dect1_k<<<dim3(L1 / 128, BATCH), blk, sm_d1>>>(A, dect1_w, dect1_b);
    dect2_k<<<dim3(L0 / 128, BATCH), blk, sm_d2>>>(dect2_w, dect2_b, out);
}

// round 12
// speedup vs baseline: 1.1162x; 1.1150x over previous
#include <cuda_runtime.h>

#define BATCH 16
#define CIN   768
#define L0    4096
#define L1    2048
#define L2    1024

__device__ float g_h1[BATCH * 32 * L1];
__device__ float g_A[BATCH * 64 * L2];
__device__ float g_B[BATCH * 64 * L2];
__device__ float g_C[BATCH * 64 * L2];
__device__ float g_d1[BATCH * 32 * L1];
__device__ float g_e2[512];
// conv1 weights, fragment-permuted, hi/lo tf32 split: [384 s][2 ct][32 lane][4 j]
__device__ float g_wph[384 * 2 * 32 * 4];
__device__ float g_wpl[384 * 2 * 32 * 4];

__device__ __forceinline__ float tf32r(float v) {
    unsigned r; asm("cvt.rna.tf32.f32 %0,%1;" : "=r"(r) : "f"(v));
    return __uint_as_float(r);
}
__device__ __forceinline__ void mma8(float* d, float4 A, unsigned b0, unsigned b1) {
    unsigned a0 = __float_as_uint(A.x), a1 = __float_as_uint(A.y);
    unsigned a2 = __float_as_uint(A.z), a3 = __float_as_uint(A.w);
    asm volatile(
        "mma.sync.aligned.m16n8k8.row.col.f32.tf32.tf32.f32 "
        "{%0,%1,%2,%3},{%4,%5,%6,%7},{%8,%9},{%0,%1,%2,%3};"
        : "+f"(d[0]), "+f"(d[1]), "+f"(d[2]), "+f"(d[3])
        : "r"(a0), "r"(a1), "r"(a2), "r"(a3), "r"(b0), "r"(b1));
}

// ---- conv1 weight prep: permute into fragment order, hi/lo split -----------
__global__ __launch_bounds__(256) void conv1_prep(const float* __restrict__ w) {
    int i = blockIdx.x * 256 + threadIdx.x;      // 384*2*32*4 = 98304
    int j = i & 3, lane = (i >> 2) & 31, ct = (i >> 7) & 1, s = i >> 8;
    int o = ct * 16 + (lane >> 2) + (j & 1) * 8;
    int k = (lane & 3) + (j >> 1) * 4;
    int c = 2 * s + (k >> 2), tap = k & 3;
    float v = w[(o * CIN + c) * 4 + tap];
    float h = tf32r(v);
    g_wph[i] = h;
    g_wpl[i] = tf32r(v - h);
}

// ---- conv1 main: register-direct 3xTF32 MMA, no smem ------------------------
// grid (32, 16): 64 positions/block, warp w covers n8 positions t0+8w..+7.
__global__ __launch_bounds__(256) void conv1_mma(const float* __restrict__ x,
                                                 const float* __restrict__ bias) {
    const int bb = blockIdx.y, t0 = blockIdx.x * 64;
    const int lane = threadIdx.x & 31;
    const int w8 = (threadIdx.x >> 5) * 8;
    const int tb = t0 + w8 + (lane >> 2);        // B-fragment position (n)
    const int gp = 2 * tb - 1 + (lane & 3);      // input position (loop-invariant)
    const bool ok = (gp >= 0) && (gp < L0);
    const float* xb = x + (size_t)bb * CIN * L0;
    const float4* Ah = (const float4*)g_wph;
    const float4* Al = (const float4*)g_wpl;

    float acc[2][4];
#pragma unroll
    for (int ct = 0; ct < 2; ct++)
#pragma unroll
        for (int j = 0; j < 4; j++) acc[ct][j] = 0.f;

#pragma unroll 4
    for (int s = 0; s < 384; ++s) {
        const float* xr = xb + (size_t)(2 * s) * L0;
        float v0 = ok ? xr[gp] : 0.f;
        float v1 = ok ? xr[L0 + gp] : 0.f;
        float h0 = tf32r(v0), l0 = tf32r(v0 - h0);
        float h1 = tf32r(v1), l1 = tf32r(v1 - h1);
        unsigned bh0 = __float_as_uint(h0), bh1 = __float_as_uint(h1);
        unsigned bl0 = __float_as_uint(l0), bl1 = __float_as_uint(l1);
#pragma unroll
        for (int ct = 0; ct < 2; ct++) {
            float4 AH = Ah[(s * 2 + ct) * 32 + lane];
            float4 AL = Al[(s * 2 + ct) * 32 + lane];
            mma8(acc[ct], AH, bh0, bh1);
            mma8(acc[ct], AH, bl0, bl1);
            mma8(acc[ct], AL, bh0, bh1);
        }
    }
    const int gr = lane >> 2;
    const int t = t0 + w8 + 2 * (lane & 3);
#pragma unroll
    for (int ct = 0; ct < 2; ct++) {
        int o0 = ct * 16 + gr, o1 = o0 + 8;
        float b0 = bias[o0], b1 = bias[o1];
        g_h1[((size_t)bb * 32 + o0) * L1 + t]     = fmaxf(acc[ct][0] + b0, 0.f);
        g_h1[((size_t)bb * 32 + o0) * L1 + t + 1] = fmaxf(acc[ct][1] + b0, 0.f);
        g_h1[((size_t)bb * 32 + o1) * L1 + t]     = fmaxf(acc[ct][2] + b1, 0.f);
        g_h1[((size_t)bb * 32 + o1) * L1 + t + 1] = fmaxf(acc[ct][3] + b1, 0.f);
    }
}

// ---- conv2: h1->out(16,64,1024), k4 s2 p1, ReLU ----------------------------
__global__ __launch_bounds__(256) void conv2_k(const float* __restrict__ w,
                                               const float* __restrict__ bias,
                                               float* __restrict__ out) {
    extern __shared__ float sm[];
    float* xs = sm;               // [32][132]
    float* ws = sm + 32 * 132;    // [32*4][68]
    const int b = blockIdx.y, t0 = blockIdx.x * 64;
    const int tid = threadIdx.x, lane = tid & 31, og = tid >> 5;
    float acc[8][2];
#pragma unroll
    for (int i = 0; i < 8; i++) { acc[i][0] = 0.f; acc[i][1] = 0.f; }

    for (int i = tid; i < 64 * 32 * 4; i += 256) {
        int k = i & 3, c = (i >> 2) & 31, o = i >> 7;
        ws[(c * 4 + k) * 68 + o] = w[((o * 32) + c) * 4 + k];
    }
    for (int i = tid; i < 32 * 130; i += 256) {
        int c = i / 130, p = i - c * 130;
        int gp = 2 * t0 - 1 + p;
        xs[c * 132 + p] = (gp >= 0 && gp < L1) ? g_h1[((b * 32) + c) * L1 + gp] : 0.f;
    }
    __syncthreads();
#pragma unroll 4
    for (int c = 0; c < 32; ++c) {
        float wr[4][8];
#pragma unroll
        for (int k = 0; k < 4; k++) {
            float4 a  = *(const float4*)&ws[(c * 4 + k) * 68 + og * 8];
            float4 b4 = *(const float4*)&ws[(c * 4 + k) * 68 + og * 8 + 4];
            wr[k][0] = a.x;  wr[k][1] = a.y;  wr[k][2] = a.z;  wr[k][3] = a.w;
            wr[k][4] = b4.x; wr[k][5] = b4.y; wr[k][6] = b4.z; wr[k][7] = b4.w;
        }
#pragma unroll
        for (int tj = 0; tj < 2; tj++) {
            const float* xr = &xs[c * 132 + 2 * (lane + 32 * tj)];
            float x0 = xr[0], x1 = xr[1], x2 = xr[2], x3 = xr[3];
#pragma unroll
            for (int oi = 0; oi < 8; oi++)
                acc[oi][tj] += wr[0][oi] * x0 + wr[1][oi] * x1 + wr[2][oi] * x2 + wr[3][oi] * x3;
        }
    }
#pragma unroll
    for (int oi = 0; oi < 8; oi++) {
        int o = og * 8 + oi;
        float bv = bias[o];
#pragma unroll
        for (int tj = 0; tj < 2; tj++)
            out[((b * 64) + o) * L2 + t0 + lane + 32 * tj] = fmaxf(acc[oi][tj] + bv, 0.f);
    }
}

// ---- generic conv 64->64, stride1, pad K/2, tile TILE ----------------------
template <int K, int TILE>
__global__ __launch_bounds__(256) void gconv_k(const float* __restrict__ in,
                                               float* __restrict__ out,
                                               const float* __restrict__ w,
                                               const float* __restrict__ bias) {
    extern __shared__ float sm[];
    constexpr int H = K / 2, W = TILE + 2 * H, XS = TILE + 4, TJ = TILE / 32;
    float* xs = sm;               // [64][XS]
    float* ws = sm + 64 * XS;     // [64*K][68]
    const int b = blockIdx.y, t0 = blockIdx.x * TILE;
    const int tid = threadIdx.x, lane = tid & 31, og = tid >> 5;
    float acc[8][TJ];
#pragma unroll
    for (int i = 0; i < 8; i++)
#pragma unroll
        for (int j = 0; j < TJ; j++) acc[i][j] = 0.f;

    for (int i = tid; i < 64 * 64 * K; i += 256) {
        int k = i % K, r = i / K, c = r & 63, o = r >> 6;
        ws[(c * K + k) * 68 + o] = w[(o * 64 + c) * K + k];
    }
    for (int i = tid; i < 64 * W; i += 256) {
        int c = i / W, p = i - c * W;
        int gp = t0 - H + p;
        xs[c * XS + p] = (gp >= 0 && gp < L2) ? in[((b * 64) + c) * L2 + gp] : 0.f;
    }
    __syncthreads();
#pragma unroll 2
    for (int c = 0; c < 64; ++c) {
        float wr[K][8];
#pragma unroll
        for (int k = 0; k < K; k++) {
            float4 a  = *(const float4*)&ws[(c * K + k) * 68 + og * 8];
            float4 b4 = *(const float4*)&ws[(c * K + k) * 68 + og * 8 + 4];
            wr[k][0] = a.x;  wr[k][1] = a.y;  wr[k][2] = a.z;  wr[k][3] = a.w;
            wr[k][4] = b4.x; wr[k][5] = b4.y; wr[k][6] = b4.z; wr[k][7] = b4.w;
        }
#pragma unroll
        for (int tj = 0; tj < TJ; tj++) {
            const float* xr = &xs[c * XS + lane + 32 * tj];
#pragma unroll
            for (int oi = 0; oi < 8; oi++) {
                float s = 0.f;
#pragma unroll
                for (int k = 0; k < K; k++) s += wr[k][oi] * xr[k];
                acc[oi][tj] += s;
            }
        }
    }
#pragma unroll
    for (int oi = 0; oi < 8; oi++) {
        int o = og * 8 + oi;
        float bv = bias[o];
#pragma unroll
        for (int tj = 0; tj < TJ; tj++)
            out[((b * 64) + o) * L2 + t0 + lane + 32 * tj] = acc[oi][tj] + bv;
    }
}

// ---- fused residual block, tile 32: out = in + w2 @ relu(conv3(relu(in))) --
__global__ __launch_bounds__(256) void res_k(const float* __restrict__ in,
                                             float* __restrict__ out,
                                             const float* __restrict__ w1,
                                             const float* __restrict__ w2,
                                             int relu_out) {
    extern __shared__ float sm[];
    float* xr  = sm;                  // [64][36] relu(in), halo 1 (p=0..33)
    float* w1s = xr + 64 * 36;        // [64c*3k][36]
    float* w2s = w1s + 64 * 3 * 36;   // [32c][68]
    float* hs  = w2s + 32 * 68;       // [32][36]
    const int bb = blockIdx.y, t0 = blockIdx.x * 32;
    const int tid = threadIdx.x, lane = tid & 31, og = tid >> 5;

    for (int i = tid; i < 64 * 3 * 32; i += 256) {
        int k = i % 3, r = i / 3, c = r & 63, o = r >> 6;
        w1s[(c * 3 + k) * 36 + o] = w1[(o * 64 + c) * 3 + k];
    }
    for (int i = tid; i < 32 * 64; i += 256) {
        int c = i >> 6, o = i & 63;
        w2s[c * 68 + o] = w2[o * 32 + c];
    }
    for (int i = tid; i < 64 * 34; i += 256) {
        int c = i / 34, p = i - c * 34;
        int gp = t0 - 1 + p;
        float v = (gp >= 0 && gp < L2) ? in[((bb * 64) + c) * L2 + gp] : 0.f;
        xr[c * 36 + p] = fmaxf(v, 0.f);
    }
    __syncthreads();
    {   // phase 1: h = relu(conv3(relu(in))), 32 mid channels (4 per warp)
        float a1[4] = {0.f, 0.f, 0.f, 0.f};
#pragma unroll 2
        for (int c = 0; c < 64; ++c) {
            const float* xp = &xr[c * 36 + lane];
            float x0 = xp[0], x1 = xp[1], x2 = xp[2];
#pragma unroll
            for (int k = 0; k < 3; k++) {
                float4 a = *(const float4*)&w1s[(c * 3 + k) * 36 + og * 4];
                float xv = (k == 0) ? x0 : (k == 1) ? x1 : x2;
                a1[0] += a.x * xv; a1[1] += a.y * xv;
                a1[2] += a.z * xv; a1[3] += a.w * xv;
            }
        }
#pragma unroll
        for (int oi = 0; oi < 4; oi++)
            hs[(og * 4 + oi) * 36 + lane] = fmaxf(a1[oi], 0.f);
    }
    __syncthreads();
    {   // phase 2: out = in + w2 @ h
        float a2[8];
#pragma unroll
        for (int i = 0; i < 8; i++) a2[i] = 0.f;
#pragma unroll 4
        for (int c = 0; c < 32; ++c) {
            float4 a  = *(const float4*)&w2s[c * 68 + og * 8];
            float4 b4 = *(const float4*)&w2s[c * 68 + og * 8 + 4];
            float hv = hs[c * 36 + lane];
            a2[0] += a.x * hv;  a2[1] += a.y * hv;
            a2[2] += a.z * hv;  a2[3] += a.w * hv;
            a2[4] += b4.x * hv; a2[5] += b4.y * hv;
            a2[6] += b4.z * hv; a2[7] += b4.w * hv;
        }
        int t = t0 + lane;
#pragma unroll
        for (int oi = 0; oi < 8; oi++) {
            int o = og * 8 + oi;
            float v = in[((bb * 64) + o) * L2 + t] + a2[oi];
            if (relu_out) v = fmaxf(v, 0.f);
            out[((bb * 64) + o) * L2 + t] = v;
        }
    }
}

// ---- codebook squared norms ------------------------------------------------
__global__ void e2_k(const float* __restrict__ emb) {
    int c = blockIdx.x * blockDim.x + threadIdx.x;
    if (c < 512) {
        float s = 0.f;
#pragma unroll 8
        for (int d = 0; d < 64; ++d) { float v = emb[c * 64 + d]; s += v * v; }
        g_e2[c] = s;
    }
}

// ---- VQ: nearest codebook row per (b,t) ------------------------------------
__global__ __launch_bounds__(256) void vq_k(const float* __restrict__ z,
                                            float* __restrict__ q,
                                            const float* __restrict__ emb) {
    extern __shared__ float sm[];
    float* zs  = sm;              // [64][33]
    float* es  = zs + 64 * 33;    // [512][17]
    float* e2s = es + 512 * 17;   // [512]
    __shared__ int idxs[32];
    const int v0 = blockIdx.x * 32;
    const int b = v0 >> 10, t0 = v0 & 1023;
    const int tid = threadIdx.x, lane = tid & 31, vg = tid >> 5;

    for (int i = tid; i < 64 * 32; i += 256) {
        int d = i >> 5, vv = i & 31;
        zs[d * 33 + vv] = z[((b * 64) + d) * L2 + t0 + vv];
    }
    for (int i = tid; i < 512; i += 256) e2s[i] = g_e2[i];

    float acc[4][16];
#pragma unroll
    for (int i = 0; i < 4; i++)
#pragma unroll
        for (int j = 0; j < 16; j++) acc[i][j] = 0.f;

    for (int k0 = 0; k0 < 64; k0 += 16) {
        __syncthreads();
        for (int i = tid; i < 512 * 4; i += 256) {
            int c = i >> 2, kq = i & 3;
            float4 v = *(const float4*)&emb[c * 64 + k0 + kq * 4];
            float* d = &es[c * 17 + kq * 4];
            d[0] = v.x; d[1] = v.y; d[2] = v.z; d[3] = v.w;
        }
        __syncthreads();
#pragma unroll
        for (int kd = 0; kd < 16; ++kd) {
            float zv0 = zs[(k0 + kd) * 33 + vg * 4 + 0];
            float zv1 = zs[(k0 + kd) * 33 + vg * 4 + 1];
            float zv2 = zs[(k0 + kd) * 33 + vg * 4 + 2];
            float zv3 = zs[(k0 + kd) * 33 + vg * 4 + 3];
#pragma unroll
            for (int cc = 0; cc < 16; ++cc) {
                float ev = es[(lane + 32 * cc) * 17 + kd];
                acc[0][cc] += zv0 * ev;
                acc[1][cc] += zv1 * ev;
                acc[2][cc] += zv2 * ev;
                acc[3][cc] += zv3 * ev;
            }
        }
    }
#pragma unroll
    for (int vv = 0; vv < 4; ++vv) {
        float mv = 3.0e38f; int mi = 0;
#pragma unroll
        for (int cc = 0; cc < 16; ++cc) {
            int c = lane + 32 * cc;
            float val = e2s[c] - 2.0f * acc[vv][cc];
            if (val < mv) { mv = val; mi = c; }
        }
        for (int off = 16; off > 0; off >>= 1) {
            float ov = __shfl_down_sync(0xffffffffu, mv, off);
            int   oi = __shfl_down_sync(0xffffffffu, mi, off);
            if (ov < mv || (ov == mv && oi < mi)) { mv = ov; mi = oi; }
        }
        if (lane == 0) idxs[vg * 4 + vv] = mi;
    }
    __syncthreads();
    for (int i = tid; i < 64 * 32; i += 256) {
        int d = i >> 5, vv = i & 31;
        q[((b * 64) + d) * L2 + t0 + vv] = emb[idxs[vv] * 64 + d];
    }
}

// ---- dect1: ConvTranspose1d 64->32, k4 s2 p1, bias, ReLU -------------------
__global__ __launch_bounds__(256) void dect1_k(const float* __restrict__ in,
                                               const float* __restrict__ w,
                                               const float* __restrict__ bias) {
    extern __shared__ float sm[];
    float* xs = sm;               // [64][68]
    float* ws = sm + 64 * 68;     // [64c*4k][36]
    const int b = blockIdx.y, t0 = blockIdx.x * 128;
    const int tid = threadIdx.x, lane = tid & 31, og = tid >> 5;
    const int s0 = t0 / 2 - 1;
    float acc[4][4];
#pragma unroll
    for (int i = 0; i < 4; i++)
#pragma unroll
        for (int j = 0; j < 4; j++) acc[i][j] = 0.f;

    for (int i = tid; i < 64 * 32 * 4; i += 256) {
        int k = i & 3, o = (i >> 2) & 31, c = i >> 7;
        ws[(c * 4 + k) * 36 + o] = w[((c * 32) + o) * 4 + k];
    }
    for (int i = tid; i < 64 * 66; i += 256) {
        int c = i / 66, ls = i - c * 66;
        int s = s0 + ls;
        xs[c * 68 + ls] = (s >= 0 && s < L2) ? in[((b * 64) + c) * L2 + s] : 0.f;
    }
    __syncthreads();
    const int khi = (lane & 1) ? 0 : 1;
    const int klo = khi + 2;
    const int lsb = ((lane + (lane & 1)) >> 1) + 1;
#pragma unroll 2
    for (int c = 0; c < 64; ++c) {
        float4 wh = *(const float4*)&ws[(c * 4 + khi) * 36 + og * 4];
        float4 wl = *(const float4*)&ws[(c * 4 + klo) * 36 + og * 4];
#pragma unroll
        for (int tj = 0; tj < 4; tj++) {
            int lh = lsb + 16 * tj;
            float xh = xs[c * 68 + lh], xl = xs[c * 68 + lh - 1];
            acc[0][tj] += wh.x * xh + wl.x * xl;
            acc[1][tj] += wh.y * xh + wl.y * xl;
            acc[2][tj] += wh.z * xh + wl.z * xl;
            acc[3][tj] += wh.w * xh + wl.w * xl;
        }
    }
#pragma unroll
    for (int oi = 0; oi < 4; oi++) {
        int o = og * 4 + oi;
        float bv = bias[o];
#pragma unroll
        for (int tj = 0; tj < 4; tj++)
            g_d1[((b * 32) + o) * L1 + t0 + lane + 32 * tj] = fmaxf(acc[oi][tj] + bv, 0.f);
    }
}

// ---- dect2: ConvTranspose1d 32->64, k4 s2 p1, bias -> d_out ----------------
__global__ __launch_bounds__(256) void dect2_k(const float* __restrict__ w,
                                               const float* __restrict__ bias,
                                               float* __restrict__ out) {
    extern __shared__ float sm[];
    float* xs = sm;               // [32][68]
    float* ws = sm + 32 * 68;     // [32c*4k][68]
    const int b = blockIdx.y, t0 = blockIdx.x * 128;
    const int tid = threadIdx.x, lane = tid & 31, og = tid >> 5;
    const int s0 = t0 / 2 - 1;
    float acc[8][4];
#pragma unroll
    for (int i = 0; i < 8; i++)
#pragma unroll
        for (int j = 0; j < 4; j++) acc[i][j] = 0.f;

    for (int i = tid; i < 32 * 64 * 4; i += 256) {
        int k = i & 3, o = (i >> 2) & 63, c = i >> 8;
        ws[(c * 4 + k) * 68 + o] = w[((c * 64) + o) * 4 + k];
    }
    for (int i = tid; i < 32 * 66; i += 256) {
        int c = i / 66, ls = i - c * 66;
        int s = s0 + ls;
        xs[c * 68 + ls] = (s >= 0 && s < L1) ? g_d1[((b * 32) + c) * L1 + s] : 0.f;
    }
    __syncthreads();
    const int khi = (lane & 1) ? 0 : 1;
    const int klo = khi + 2;
    const int lsb = ((lane + (lane & 1)) >> 1) + 1;
#pragma unroll 2
    for (int c = 0; c < 32; ++c) {
        float4 wh0 = *(const float4*)&ws[(c * 4 + khi) * 68 + og * 8];
        float4 wh1 = *(const float4*)&ws[(c * 4 + khi) * 68 + og * 8 + 4];
        float4 wl0 = *(const float4*)&ws[(c * 4 + klo) * 68 + og * 8];
        float4 wl1 = *(const float4*)&ws[(c * 4 + klo) * 68 + og * 8 + 4];
        float wh[8] = {wh0.x, wh0.y, wh0.z, wh0.w, wh1.x, wh1.y, wh1.z, wh1.w};
        float wl[8] = {wl0.x, wl0.y, wl0.z, wl0.w, wl1.x, wl1.y, wl1.z, wl1.w};
#pragma unroll
        for (int tj = 0; tj < 4; tj++) {
            int lh = lsb + 16 * tj;
            float xh = xs[c * 68 + lh], xl = xs[c * 68 + lh - 1];
#pragma unroll
            for (int oi = 0; oi < 8; oi++)
                acc[oi][tj] += wh[oi] * xh + wl[oi] * xl;
        }
    }
#pragma unroll
    for (int oi = 0; oi < 8; oi++) {
        int o = og * 8 + oi;
        float bv = bias[o];
#pragma unroll
        for (int tj = 0; tj < 4; tj++)
            out[((b * 64) + o) * L0 + t0 + lane + 32 * tj] = acc[oi][tj] + bv;
    }
}

extern "C" void kernel_launch(void* const* d_in, const int* in_sizes, int n_in,
                              void* d_out, int out_size) {
    const float* x         = (const float*)d_in[0];
    const float* enc_w1    = (const float*)d_in[1];
    const float* enc_b1    = (const float*)d_in[2];
    const float* enc_w2    = (const float*)d_in[3];
    const float* enc_b2    = (const float*)d_in[4];
    const float* enc_w3    = (const float*)d_in[5];
    const float* enc_b3    = (const float*)d_in[6];
    const float* enc_r0_w1 = (const float*)d_in[7];
    const float* enc_r0_w2 = (const float*)d_in[8];
    const float* enc_r1_w1 = (const float*)d_in[9];
    const float* enc_r1_w2 = (const float*)d_in[10];
    const float* prevq_w   = (const float*)d_in[11];
    const float* prevq_b   = (const float*)d_in[12];
    const float* emb       = (const float*)d_in[13];
    const float* dec_w1    = (const float*)d_in[14];
    const float* dec_b1    = (const float*)d_in[15];
    const float* dec_r0_w1 = (const float*)d_in[16];
    const float* dec_r0_w2 = (const float*)d_in[17];
    const float* dec_r1_w1 = (const float*)d_in[18];
    const float* dec_r1_w2 = (const float*)d_in[19];
    const float* dect1_w   = (const float*)d_in[20];
    const float* dect1_b   = (const float*)d_in[21];
    const float* dect2_w   = (const float*)d_in[22];
    const float* dect2_b   = (const float*)d_in[23];
    float* out = (float*)d_out;

    float *A, *B, *C;
    cudaGetSymbolAddress((void**)&A, g_A);
    cudaGetSymbolAddress((void**)&B, g_B);
    cudaGetSymbolAddress((void**)&C, g_C);

    cudaFuncSetAttribute(conv2_k, cudaFuncAttributeMaxDynamicSharedMemorySize, 65536);
    cudaFuncSetAttribute(gconv_k<3, 32>, cudaFuncAttributeMaxDynamicSharedMemorySize, 98304);
    cudaFuncSetAttribute(gconv_k<1, 64>, cudaFuncAttributeMaxDynamicSharedMemorySize, 65536);
    cudaFuncSetAttribute(res_k, cudaFuncAttributeMaxDynamicSharedMemorySize, 65536);
    cudaFuncSetAttribute(dect1_k, cudaFuncAttributeMaxDynamicSharedMemorySize, 65536);

    dim3 blk(256);
    size_t sm_c2  = (32 * 132 + 128 * 68) * 4;
    size_t sm_g3  = (64 * 36 + 64 * 3 * 68) * 4;
    size_t sm_g1  = (64 * 68 + 64 * 68) * 4;
    size_t sm_res = (64 * 36 + 64 * 3 * 36 + 32 * 68 + 32 * 36) * 4;
    size_t sm_vq  = (64 * 33 + 512 * 17 + 512) * 4;
    size_t sm_d1  = (64 * 68 + 256 * 36) * 4;
    size_t sm_d2  = (32 * 68 + 128 * 68) * 4;
    dim3 gg32(L2 / 32, BATCH);
    dim3 gg64(L2 / 64, BATCH);

    // encoder
    conv1_prep<<<384, 256>>>(enc_w1);
    conv1_mma<<<dim3(L1 / 64, BATCH), blk>>>(x, enc_b1);
    conv2_k<<<gg64, blk, sm_c2>>>(enc_w2, enc_b2, A);
    gconv_k<3, 32><<<gg32, blk, sm_g3>>>(A, B, enc_w3, enc_b3);
    res_k<<<gg32, blk, sm_res>>>(B, A, enc_r0_w1, enc_r0_w2, 0);
    res_k<<<gg32, blk, sm_res>>>(A, B, enc_r1_w1, enc_r1_w2, 1);
    gconv_k<1, 64><<<gg64, blk, sm_g1>>>(B, A, prevq_w, prevq_b);
    // VQ
    e2_k<<<2, 256>>>(emb);
    vq_k<<<BATCH * L2 / 32, blk, sm_vq>>>(A, C, emb);
    // decoder
    gconv_k<3, 32><<<gg32, blk, sm_g3>>>(C, A, dec_w1, dec_b1);
    res_k<<<gg32, blk, sm_res>>>(A, B, dec_r0_w1, dec_r0_w2, 0);
    res_k<<<gg32, blk, sm_res>>>(B, A, dec_r1_w1, dec_r1_w2, 1);
    dect1_k<<<dim3(L1 / 128, BATCH), blk, sm_d1>>>(A, dect1_w, dect1_b);
    dect2_k<<<dim3(L0 / 128, BATCH), blk, sm_d2>>>(dect2_w, dect2_b, out);
}